// round 2
// baseline (speedup 1.0000x reference)
#include <cuda_runtime.h>
#include <math.h>

// ---------------- problem constants ----------------
#define BB   64
#define TT   256
#define EMBD 256
#define PROJ 256
#define RDIM 2048
#define HH   512
#define G4   2048
#define DIN  512
#define KOO  3
#define KRR  2

// output layout (float32): outputs[B,T,2H], hidden_h[1,B,2H], hidden_c[1,B,2H], embedded[B,T,512]
#define OUT0_N  (64ULL*256ULL*1024ULL)          // 16,777,216
#define OUT1_O  (OUT0_N)                        // + 65,536
#define OUT2_O  (OUT1_O + 64ULL*1024ULL)
#define OUT3_O  (OUT2_O + 64ULL*1024ULL)

// ---------------- device scratch (no allocs allowed) ----------------
__device__ float        g_xw[2][BB*TT][G4];      // 268 MB: precomputed x@Wi^T + bias per direction
__device__ float        g_h[2][2][BB][HH];       // [dir][phase][b][h] double-buffered hidden state
__device__ unsigned int g_bar[2];                // per-direction step barrier
__device__ int          g_mask_mode;             // 0=int32, 1=byte, 2=float32

// ---------------- act_mask dtype sniffer ----------------
__global__ void k_sniff(const unsigned int* am) {
    __shared__ int s_mode;
    if (threadIdx.x == 0) s_mode = 0;
    __syncthreads();
    int mode = 0;
    for (int i = threadIdx.x; i < 4096; i += blockDim.x) {
        unsigned v = am[i];
        if (v == 0x3f800000u)      mode = 2;          // float 1.0
        else if (v > 1u && mode < 2) mode = 1;        // packed bytes
    }
    if (mode) atomicMax(&s_mode, mode);
    __syncthreads();
    if (threadIdx.x == 0) g_mask_mode = s_mode;
}

__device__ __forceinline__ int get_mask(const void* am, int idx) {
    int mode = g_mask_mode;
    if (mode == 1) return ((const unsigned char*)am)[idx] != 0;
    if (mode == 2) return ((const float*)am)[idx] != 0.0f;
    return ((const int*)am)[idx] != 0;
}

// ---------------- init: zero outputs region + state + barriers ----------------
__global__ void k_init(float* out0) {
    size_t stride = (size_t)gridDim.x * blockDim.x;
    size_t tid = (size_t)blockIdx.x * blockDim.x + threadIdx.x;
    float4 z = make_float4(0.f, 0.f, 0.f, 0.f);
    float4* o4 = (float4*)out0;
    for (size_t i = tid; i < OUT0_N / 4; i += stride) o4[i] = z;
    float* gh = &g_h[0][0][0][0];
    for (size_t i = tid; i < 2ULL * 2ULL * BB * HH; i += stride) gh[i] = 0.f;
    if (tid < 2) g_bar[tid] = 0u;
}

// ---------------- embedding (cols 0..255 of embedded) ----------------
__global__ void k_embed(const void* am, const int* act_ids, const int* obs_ids,
                        const float* act_emb, const float* obs_emb, float* emb_out) {
    int idx = blockIdx.x * blockDim.x + threadIdx.x;   // over 16384 * 64 float4s
    if (idx >= BB * TT * 64) return;
    int bt = idx >> 6;
    int c4 = (idx & 63) * 4;
    float4 v;
    if (get_mask(am, bt)) {
        int id = act_ids[bt];                           // 1..3, never 0
        v = *(const float4*)(act_emb + (size_t)id * EMBD + c4);
    } else {
        v = make_float4(0.f, 0.f, 0.f, 0.f);
#pragma unroll
        for (int k = 0; k < KOO; ++k) {
            int id = obs_ids[bt * KOO + k];
            if (id != 0) {                              // padding_idx 0 -> zero row
                float4 e = *(const float4*)(obs_emb + (size_t)id * EMBD + c4);
                v.x += e.x; v.y += e.y; v.z += e.z; v.w += e.w;
            }
        }
    }
    *(float4*)(emb_out + (size_t)bt * 512 + c4) = v;
}

// ---------------- res GEMM: embedded[:,256:512] = (f0+f1) @ W_res^T + 2*b_res (masked->0) ----------------
// BM=128, BN=64, BK=8, 256 threads, thread tile 8x4
__global__ __launch_bounds__(256) void k_res(const float* feats, const float* W,
                                             const float* b_res, const void* am,
                                             float* emb_out) {
    __shared__ float As[8][128];
    __shared__ float Bs[8][64];
    int m0 = blockIdx.y * 128;
    int n0 = blockIdx.x * 64;
    int tid = threadIdx.x;
    int arow = tid >> 1, acol = (tid & 1) * 4;
    int brow = tid >> 2, bcol = (tid & 3) * 2;
    int tx = tid & 15, ty = tid >> 4;
    float acc[8][4];
#pragma unroll
    for (int i = 0; i < 8; ++i)
#pragma unroll
        for (int j = 0; j < 4; ++j) acc[i][j] = 0.f;

    const float* Abase = feats + (size_t)(m0 + arow) * (KRR * RDIM);
    const float* Bbase = W + (size_t)(n0 + brow) * RDIM;

    for (int k0 = 0; k0 < RDIM; k0 += 8) {
        float4 a0 = *(const float4*)(Abase + k0 + acol);
        float4 a1 = *(const float4*)(Abase + RDIM + k0 + acol);
        float2 bv = *(const float2*)(Bbase + k0 + bcol);
        __syncthreads();
        As[acol + 0][arow] = a0.x + a1.x;
        As[acol + 1][arow] = a0.y + a1.y;
        As[acol + 2][arow] = a0.z + a1.z;
        As[acol + 3][arow] = a0.w + a1.w;
        Bs[bcol + 0][brow] = bv.x;
        Bs[bcol + 1][brow] = bv.y;
        __syncthreads();
#pragma unroll
        for (int kk = 0; kk < 8; ++kk) {
            float4 m0v = *(float4*)&As[kk][ty * 8];
            float4 m1v = *(float4*)&As[kk][ty * 8 + 4];
            float4 nv  = *(float4*)&Bs[kk][tx * 4];
            float rm[8] = {m0v.x, m0v.y, m0v.z, m0v.w, m1v.x, m1v.y, m1v.z, m1v.w};
            float rn[4] = {nv.x, nv.y, nv.z, nv.w};
#pragma unroll
            for (int i = 0; i < 8; ++i)
#pragma unroll
                for (int j = 0; j < 4; ++j) acc[i][j] += rm[i] * rn[j];
        }
    }
#pragma unroll
    for (int i = 0; i < 8; ++i) {
        int m = m0 + ty * 8 + i;
        int msk = get_mask(am, m);
#pragma unroll
        for (int j = 0; j < 4; ++j) {
            int n = n0 + tx * 4 + j;
            float val = msk ? 0.f : (acc[i][j] + 2.f * b_res[n]);
            emb_out[(size_t)m * 512 + 256 + n] = val;
        }
    }
}

// ---------------- xw GEMM: g_xw[dir][b*T+s][:] = x_dir[b,s,:] @ Wi^T + (bi+bh) ----------------
// dir 0: x = embedded[b,s]; dir 1: x = embedded[b, max(len-1-s,0)]
// BM=128 (one tile = one b, half of T), BN=128, BK=8, 256 threads, 8x8 tiles. Skips fully-invalid tiles.
__global__ __launch_bounds__(256) void k_xw(const float* emb,
                                            const float* Wi_f, const float* bi_f, const float* bh_f,
                                            const float* Wi_b, const float* bi_b, const float* bh_b,
                                            const int* lengths) {
    int dir = blockIdx.z;
    const float* Wi = dir ? Wi_b : Wi_f;
    const float* bi = dir ? bi_b : bi_f;
    const float* bh = dir ? bh_b : bh_f;
    int m0 = blockIdx.y * 128;
    int n0 = blockIdx.x * 128;
    int b = m0 >> 8;
    int s0 = m0 & 255;
    int lenb = lengths[b];
    if (s0 >= lenb) return;   // whole tile unused for this direction

    __shared__ float As[8][128];
    __shared__ float Bs[8][128];
    int tid = threadIdx.x;
    int arow = tid >> 1, acol = (tid & 1) * 4;
    int tx = tid & 15, ty = tid >> 4;

    int s = s0 + arow;
    int t = dir ? (lenb - 1 - s) : s;
    if (t < 0) t = 0;
    const float* Arow = emb + ((size_t)(b * TT + t)) * 512;
    const float* Brow = Wi + (size_t)(n0 + arow) * 512;   // reuse same mapping for B rows

    float acc[8][8];
#pragma unroll
    for (int i = 0; i < 8; ++i)
#pragma unroll
        for (int j = 0; j < 8; ++j) acc[i][j] = 0.f;

    for (int k0 = 0; k0 < 512; k0 += 8) {
        float4 av = *(const float4*)(Arow + k0 + acol);
        float4 bv = *(const float4*)(Brow + k0 + acol);
        __syncthreads();
        As[acol + 0][arow] = av.x; As[acol + 1][arow] = av.y;
        As[acol + 2][arow] = av.z; As[acol + 3][arow] = av.w;
        Bs[acol + 0][arow] = bv.x; Bs[acol + 1][arow] = bv.y;
        Bs[acol + 2][arow] = bv.z; Bs[acol + 3][arow] = bv.w;
        __syncthreads();
#pragma unroll
        for (int kk = 0; kk < 8; ++kk) {
            float4 a0v = *(float4*)&As[kk][ty * 8];
            float4 a1v = *(float4*)&As[kk][ty * 8 + 4];
            float4 b0v = *(float4*)&Bs[kk][tx * 8];
            float4 b1v = *(float4*)&Bs[kk][tx * 8 + 4];
            float rm[8] = {a0v.x, a0v.y, a0v.z, a0v.w, a1v.x, a1v.y, a1v.z, a1v.w};
            float rn[8] = {b0v.x, b0v.y, b0v.z, b0v.w, b1v.x, b1v.y, b1v.z, b1v.w};
#pragma unroll
            for (int i = 0; i < 8; ++i)
#pragma unroll
                for (int j = 0; j < 8; ++j) acc[i][j] += rm[i] * rn[j];
        }
    }
#pragma unroll
    for (int i = 0; i < 8; ++i) {
        int m = m0 + ty * 8 + i;
        float* orow = &g_xw[dir][m][0];
#pragma unroll
        for (int j = 0; j < 8; ++j) {
            int n = n0 + tx * 8 + j;
            orow[n] = acc[i][j] + bi[n] + bh[n];
        }
    }
}

// ---------------- persistent recurrence ----------------
// 128 CTAs: blocks [0,64) = forward, [64,128) = backward. Each CTA owns 8 h-columns
// (32 gate rows). Wh slice lives in registers (4 rows x 16 k per thread); h streamed from L2.
__global__ __launch_bounds__(256, 1) void k_recur(const float* Wh_f, const float* Wh_b,
                                                  const int* lengths, float* d_out) {
    int dir = blockIdx.x >> 6;
    int cid = blockIdx.x & 63;
    int j0 = cid * 8;
    const float* Wh = dir ? Wh_b : Wh_f;
    int tid = threadIdx.x;
    int w = tid >> 5, lane = tid & 31;

    __shared__ int   len_s[64];
    __shared__ float gates_s[64][32];   // [b][lr], lr = gate*8 + jj
    __shared__ float c_s[64][8];

    if (tid < 64) len_s[tid] = lengths[tid];
    for (int i = tid; i < 512; i += 256) c_s[i >> 3][i & 7] = 0.f;

    // weight registers: warp w owns local rows lr = 4w..4w+3; lane owns k [lane*16, lane*16+16)
    float wr0[16], wr1[16], wr2[16], wr3[16];
#pragma unroll
    for (int r = 0; r < 4; ++r) {
        int lr = w * 4 + r;
        int grow = (lr >> 3) * 512 + j0 + (lr & 7);
        const float* src = Wh + (size_t)grow * 512 + lane * 16;
        float* dst = (r == 0) ? wr0 : (r == 1) ? wr1 : (r == 2) ? wr2 : wr3;
#pragma unroll
        for (int q = 0; q < 4; ++q) {
            float4 v = *(const float4*)(src + q * 4);
            dst[q * 4 + 0] = v.x; dst[q * 4 + 1] = v.y;
            dst[q * 4 + 2] = v.z; dst[q * 4 + 3] = v.w;
        }
    }
    __syncthreads();

    float* hbase = &g_h[dir][0][0][0];
    int nact = 64;
    int fb = 0;

    for (int t = 0; t < TT; ++t) {
        while (nact > 0 && len_s[nact - 1] <= t) --nact;
        if (nact == 0) break;
        const float* hr = hbase + (size_t)(t & 1) * (BB * HH);
        float*       hw = hbase + (size_t)((t + 1) & 1) * (BB * HH);

        // ---- Wh @ h for active batches ----
        {
            const float* hp = hr + lane * 16;
            float4 p0 = *(const float4*)(hp + 0);
            float4 p1 = *(const float4*)(hp + 4);
            float4 p2 = *(const float4*)(hp + 8);
            float4 p3 = *(const float4*)(hp + 12);
            for (int b = 0; b < nact; ++b) {
                float hv[16] = {p0.x, p0.y, p0.z, p0.w, p1.x, p1.y, p1.z, p1.w,
                                p2.x, p2.y, p2.z, p2.w, p3.x, p3.y, p3.z, p3.w};
                if (b + 1 < nact) {
                    const float* hn = hr + (size_t)(b + 1) * 512 + lane * 16;
                    p0 = *(const float4*)(hn + 0);
                    p1 = *(const float4*)(hn + 4);
                    p2 = *(const float4*)(hn + 8);
                    p3 = *(const float4*)(hn + 12);
                }
                float a0 = 0.f, a1 = 0.f, a2 = 0.f, a3 = 0.f;
#pragma unroll
                for (int q = 0; q < 16; ++q) {
                    a0 += wr0[q] * hv[q];
                    a1 += wr1[q] * hv[q];
                    a2 += wr2[q] * hv[q];
                    a3 += wr3[q] * hv[q];
                }
#pragma unroll
                for (int off = 16; off; off >>= 1) {
                    a0 += __shfl_xor_sync(0xffffffffu, a0, off);
                    a1 += __shfl_xor_sync(0xffffffffu, a1, off);
                    a2 += __shfl_xor_sync(0xffffffffu, a2, off);
                    a3 += __shfl_xor_sync(0xffffffffu, a3, off);
                }
                if (lane == 0) {
                    gates_s[b][w * 4 + 0] = a0;
                    gates_s[b][w * 4 + 1] = a1;
                    gates_s[b][w * 4 + 2] = a2;
                    gates_s[b][w * 4 + 3] = a3;
                }
            }
        }
        __syncthreads();

        // ---- elementwise gate math + state update ----
#pragma unroll
        for (int rep = 0; rep < 2; ++rep) {
            int it = tid + rep * 256;
            int b = it >> 3, jj = it & 7;
            int col = j0 + jj;
            float hn;
            if (b < nact) {
                const float* xwrow = &g_xw[dir][b * TT + t][0];
                float gi = gates_s[b][jj]      + xwrow[col];
                float gf = gates_s[b][8 + jj]  + xwrow[512 + col];
                float gg = gates_s[b][16 + jj] + xwrow[1024 + col];
                float go = gates_s[b][24 + jj] + xwrow[1536 + col];
                gi = 1.f / (1.f + __expf(-gi));
                gf = 1.f / (1.f + __expf(-gf));
                gg = tanhf(gg);
                go = 1.f / (1.f + __expf(-go));
                float c = gf * c_s[b][jj] + gi * gg;
                c_s[b][jj] = c;
                hn = go * tanhf(c);
                int tout = dir ? (len_s[b] - 1 - t) : t;
                d_out[((size_t)(b * TT + tout)) * 1024 + (size_t)dir * 512 + col] = hn;
            } else {
                hn = hr[(size_t)b * 512 + col];   // propagate frozen state
            }
            hw[(size_t)b * 512 + col] = hn;
        }
        fb = (t + 1) & 1;

        // ---- inter-CTA step barrier (per direction) ----
        __threadfence();
        __syncthreads();
        if (tid == 0) {
            atomicAdd(&g_bar[dir], 1u);
            unsigned tgt = (unsigned)(t + 1) * 64u;
            while (*(volatile unsigned*)&g_bar[dir] < tgt) {
                asm volatile("nanosleep.u32 64;");
            }
            __threadfence();
        }
        __syncthreads();
    }

    // ---- final hidden h / c ----
    for (int i = tid; i < 512; i += 256) {
        int b = i >> 3, jj = i & 7;
        int col = j0 + jj;
        float hval = hbase[(size_t)fb * (BB * HH) + (size_t)b * 512 + col];
        d_out[OUT1_O + (size_t)b * 1024 + (size_t)dir * 512 + col] = hval;
        d_out[OUT2_O + (size_t)b * 1024 + (size_t)dir * 512 + col] = c_s[b][jj];
    }
}

// ---------------- launch ----------------
extern "C" void kernel_launch(void* const* d_in, const int* in_sizes, int n_in,
                              void* d_out, int out_size) {
    const void*  act_mask  = d_in[0];
    const int*   act_ids   = (const int*)d_in[1];
    const int*   obs_ids   = (const int*)d_in[2];
    const float* res_feats = (const float*)d_in[3];
    const int*   lengths   = (const int*)d_in[4];
    const float* act_emb   = (const float*)d_in[5];
    const float* obs_emb   = (const float*)d_in[6];
    const float* W_res     = (const float*)d_in[7];
    const float* b_res     = (const float*)d_in[8];
    const float* Wi_f      = (const float*)d_in[9];
    const float* Wh_f      = (const float*)d_in[10];
    const float* bi_f      = (const float*)d_in[11];
    const float* bh_f      = (const float*)d_in[12];
    const float* Wi_b      = (const float*)d_in[13];
    const float* Wh_b      = (const float*)d_in[14];
    const float* bi_b      = (const float*)d_in[15];
    const float* bh_b      = (const float*)d_in[16];

    float* out = (float*)d_out;
    float* emb_out = out + OUT3_O;

    k_sniff<<<1, 256>>>((const unsigned int*)act_mask);
    k_init<<<2048, 256>>>(out);
    k_embed<<<(BB * TT * 64 + 255) / 256, 256>>>(act_mask, act_ids, obs_ids,
                                                 act_emb, obs_emb, emb_out);
    {
        dim3 g(PROJ / 64, (BB * TT) / 128, 1);
        k_res<<<g, 256>>>(res_feats, W_res, b_res, act_mask, emb_out);
    }
    {
        dim3 g(G4 / 128, (BB * TT) / 128, 2);
        k_xw<<<g, 256>>>(emb_out, Wi_f, bi_f, bh_f, Wi_b, bi_b, bh_b, lengths);
    }
    k_recur<<<128, 256>>>(Wh_f, Wh_b, lengths, out);
}

// round 3
// speedup vs baseline: 1.0980x; 1.0980x over previous
#include <cuda_runtime.h>
#include <math.h>

// ---------------- problem constants ----------------
#define BB   64
#define TT   256
#define EMBD 256
#define PROJ 256
#define RDIM 2048
#define HH   512
#define G4   2048
#define DIN  512
#define KOO  3
#define KRR  2

typedef unsigned long long u64;

// output layout (float32): outputs[B,T,2H], hidden_h[1,B,2H], hidden_c[1,B,2H], embedded[B,T,512]
#define OUT0_N  (64ULL*256ULL*1024ULL)
#define OUT1_O  (OUT0_N)
#define OUT2_O  (OUT1_O + 64ULL*1024ULL)
#define OUT3_O  (OUT2_O + 64ULL*1024ULL)

// ---------------- device scratch ----------------
__device__ __align__(16) float g_xw[2][BB*TT][G4];   // precomputed x@Wi^T + bias per direction
__device__ __align__(16) float g_h[2][2][BB][HH];    // [dir][phase][b][h]
__device__ unsigned int g_bar[2];
__device__ int          g_mask_mode;

// ---------------- f32x2 helpers ----------------
__device__ __forceinline__ void FMA2(u64& acc, u64 a, u64 b) {
    asm("fma.rn.f32x2 %0, %1, %2, %0;" : "+l"(acc) : "l"(a), "l"(b));
}
__device__ __forceinline__ u64 SPLAT2(float x) {
    u64 r; asm("mov.b64 %0, {%1, %2};" : "=l"(r) : "f"(x), "f"(x)); return r;
}
__device__ __forceinline__ float HADD2(u64 v) {
    float lo, hi; asm("mov.b64 {%0, %1}, %2;" : "=f"(lo), "=f"(hi) : "l"(v)); return lo + hi;
}
__device__ __forceinline__ void UNPACK2(u64 v, float& lo, float& hi) {
    asm("mov.b64 {%0, %1}, %2;" : "=f"(lo), "=f"(hi) : "l"(v));
}

// ---------------- act_mask dtype sniffer ----------------
__global__ void k_sniff(const unsigned int* am) {
    __shared__ int s_mode;
    if (threadIdx.x == 0) s_mode = 0;
    __syncthreads();
    int mode = 0;
    for (int i = threadIdx.x; i < 4096; i += blockDim.x) {
        unsigned v = am[i];
        if (v == 0x3f800000u)      mode = 2;
        else if (v > 1u && mode < 2) mode = 1;
    }
    if (mode) atomicMax(&s_mode, mode);
    __syncthreads();
    if (threadIdx.x == 0) g_mask_mode = s_mode;
}

__device__ __forceinline__ int get_mask(const void* am, int idx) {
    int mode = g_mask_mode;
    if (mode == 1) return ((const unsigned char*)am)[idx] != 0;
    if (mode == 2) return ((const float*)am)[idx] != 0.0f;
    return ((const int*)am)[idx] != 0;
}

// ---------------- init ----------------
__global__ void k_init(float* out0) {
    size_t stride = (size_t)gridDim.x * blockDim.x;
    size_t tid = (size_t)blockIdx.x * blockDim.x + threadIdx.x;
    float4 z = make_float4(0.f, 0.f, 0.f, 0.f);
    float4* o4 = (float4*)out0;
    for (size_t i = tid; i < OUT0_N / 4; i += stride) o4[i] = z;
    float* gh = &g_h[0][0][0][0];
    for (size_t i = tid; i < 2ULL * 2ULL * BB * HH; i += stride) gh[i] = 0.f;
    if (tid < 2) g_bar[tid] = 0u;
}

// ---------------- embedding ----------------
__global__ void k_embed(const void* am, const int* act_ids, const int* obs_ids,
                        const float* act_emb, const float* obs_emb, float* emb_out) {
    int idx = blockIdx.x * blockDim.x + threadIdx.x;
    if (idx >= BB * TT * 64) return;
    int bt = idx >> 6;
    int c4 = (idx & 63) * 4;
    float4 v;
    if (get_mask(am, bt)) {
        int id = act_ids[bt];
        v = *(const float4*)(act_emb + (size_t)id * EMBD + c4);
    } else {
        v = make_float4(0.f, 0.f, 0.f, 0.f);
#pragma unroll
        for (int k = 0; k < KOO; ++k) {
            int id = obs_ids[bt * KOO + k];
            if (id != 0) {
                float4 e = *(const float4*)(obs_emb + (size_t)id * EMBD + c4);
                v.x += e.x; v.y += e.y; v.z += e.z; v.w += e.w;
            }
        }
    }
    *(float4*)(emb_out + (size_t)bt * 512 + c4) = v;
}

// ---------------- res GEMM (f32x2) ----------------
// BM=128, BN=64, BK=8, 256 threads; acc pairs rows: acc2[4][4]
__global__ __launch_bounds__(256) void k_res(const float* feats, const float* W,
                                             const float* b_res, const void* am,
                                             float* emb_out) {
    __shared__ float As[8][128];
    __shared__ float Bs[8][64];
    __shared__ float bias_s[64];
    int m0 = blockIdx.y * 128;
    int n0 = blockIdx.x * 64;
    int tid = threadIdx.x;
    if (tid < 64) bias_s[tid] = 2.f * b_res[n0 + tid];
    int arow = tid >> 1, acol = (tid & 1) * 4;
    int brow = tid >> 2, bcol = (tid & 3) * 2;
    int tx = tid & 15, ty = tid >> 4;
    u64 acc2[4][4];
#pragma unroll
    for (int i = 0; i < 4; ++i)
#pragma unroll
        for (int j = 0; j < 4; ++j) acc2[i][j] = 0ULL;

    const float* Abase = feats + (size_t)(m0 + arow) * (KRR * RDIM);
    const float* Bbase = W + (size_t)(n0 + brow) * RDIM;

    for (int k0 = 0; k0 < RDIM; k0 += 8) {
        float4 a0 = *(const float4*)(Abase + k0 + acol);
        float4 a1 = *(const float4*)(Abase + RDIM + k0 + acol);
        float2 bv = *(const float2*)(Bbase + k0 + bcol);
        __syncthreads();
        As[acol + 0][arow] = a0.x + a1.x;
        As[acol + 1][arow] = a0.y + a1.y;
        As[acol + 2][arow] = a0.z + a1.z;
        As[acol + 3][arow] = a0.w + a1.w;
        Bs[bcol + 0][brow] = bv.x;
        Bs[bcol + 1][brow] = bv.y;
        __syncthreads();
#pragma unroll
        for (int kk = 0; kk < 8; ++kk) {
            const ulonglong2* pA = (const ulonglong2*)&As[kk][ty * 8];
            ulonglong2 qa0 = pA[0], qa1 = pA[1];
            u64 ra[4] = {qa0.x, qa0.y, qa1.x, qa1.y};
            float4 nv = *(float4*)&Bs[kk][tx * 4];
            u64 rb[4] = {SPLAT2(nv.x), SPLAT2(nv.y), SPLAT2(nv.z), SPLAT2(nv.w)};
#pragma unroll
            for (int i = 0; i < 4; ++i)
#pragma unroll
                for (int j = 0; j < 4; ++j) FMA2(acc2[i][j], ra[i], rb[j]);
        }
    }
#pragma unroll
    for (int i2 = 0; i2 < 4; ++i2) {
        int me = m0 + ty * 8 + i2 * 2;
        int msk_e = get_mask(am, me);
        int msk_o = get_mask(am, me + 1);
        float* oe = emb_out + (size_t)me * 512 + 256;
        float* oo = oe + 512;
#pragma unroll
        for (int j = 0; j < 4; ++j) {
            int n = tx * 4 + j;
            float lo, hi; UNPACK2(acc2[i2][j], lo, hi);
            oe[n0 + n] = msk_e ? 0.f : (lo + bias_s[n]);
            oo[n0 + n] = msk_o ? 0.f : (hi + bias_s[n]);
        }
    }
}

// ---------------- xw GEMM (f32x2) ----------------
// BM=128 (one b, half T), BN=128, BK=8, 256 threads; acc2[4][8] pairs rows
__global__ __launch_bounds__(256) void k_xw(const float* emb,
                                            const float* Wi_f, const float* bi_f, const float* bh_f,
                                            const float* Wi_b, const float* bi_b, const float* bh_b,
                                            const int* lengths) {
    int dir = blockIdx.z;
    const float* Wi = dir ? Wi_b : Wi_f;
    const float* bi = dir ? bi_b : bi_f;
    const float* bh = dir ? bh_b : bh_f;
    int m0 = blockIdx.y * 128;
    int n0 = blockIdx.x * 128;
    int b = m0 >> 8;
    int s0 = m0 & 255;
    int lenb = lengths[b];
    if (s0 >= lenb) return;

    __shared__ float As[8][128];
    __shared__ float Bs[8][128];
    __shared__ float bias_s[128];
    int tid = threadIdx.x;
    if (tid < 128) bias_s[tid] = bi[n0 + tid] + bh[n0 + tid];
    int arow = tid >> 1, acol = (tid & 1) * 4;
    int tx = tid & 15, ty = tid >> 4;

    int s = s0 + arow;
    int t = dir ? (lenb - 1 - s) : s;
    if (t < 0) t = 0;
    const float* Arow = emb + ((size_t)(b * TT + t)) * 512;
    const float* Brow = Wi + (size_t)(n0 + arow) * 512;

    u64 acc2[4][8];
#pragma unroll
    for (int i = 0; i < 4; ++i)
#pragma unroll
        for (int j = 0; j < 8; ++j) acc2[i][j] = 0ULL;

    for (int k0 = 0; k0 < 512; k0 += 8) {
        float4 av = *(const float4*)(Arow + k0 + acol);
        float4 bv = *(const float4*)(Brow + k0 + acol);
        __syncthreads();
        As[acol + 0][arow] = av.x; As[acol + 1][arow] = av.y;
        As[acol + 2][arow] = av.z; As[acol + 3][arow] = av.w;
        Bs[acol + 0][arow] = bv.x; Bs[acol + 1][arow] = bv.y;
        Bs[acol + 2][arow] = bv.z; Bs[acol + 3][arow] = bv.w;
        __syncthreads();
#pragma unroll
        for (int kk = 0; kk < 8; ++kk) {
            const ulonglong2* pA = (const ulonglong2*)&As[kk][ty * 8];
            ulonglong2 qa0 = pA[0], qa1 = pA[1];
            u64 ra[4] = {qa0.x, qa0.y, qa1.x, qa1.y};
            float4 b0v = *(float4*)&Bs[kk][tx * 8];
            float4 b1v = *(float4*)&Bs[kk][tx * 8 + 4];
            u64 rb[8] = {SPLAT2(b0v.x), SPLAT2(b0v.y), SPLAT2(b0v.z), SPLAT2(b0v.w),
                         SPLAT2(b1v.x), SPLAT2(b1v.y), SPLAT2(b1v.z), SPLAT2(b1v.w)};
#pragma unroll
            for (int i = 0; i < 4; ++i)
#pragma unroll
                for (int j = 0; j < 8; ++j) FMA2(acc2[i][j], ra[i], rb[j]);
        }
    }
#pragma unroll
    for (int i2 = 0; i2 < 4; ++i2) {
        int me = m0 + ty * 8 + i2 * 2;
        float* oe = &g_xw[dir][me][0];
        float* oo = &g_xw[dir][me + 1][0];
#pragma unroll
        for (int j = 0; j < 8; ++j) {
            int n = tx * 8 + j;
            float lo, hi; UNPACK2(acc2[i2][j], lo, hi);
            float bb = bias_s[n];
            oe[n0 + n] = lo + bb;
            oo[n0 + n] = hi + bb;
        }
    }
}

// ---------------- persistent recurrence (f32x2 + 3-round shuffle + smem partials) ----------------
// 128 CTAs: [0,64)=fwd, [64,128)=bwd. CTA owns 8 h-cols (32 gate rows).
// Warp w owns rows 4w..4w+3; lane owns k-slice [lane*16, lane*16+16) packed as 8 f32x2.
__global__ __launch_bounds__(256, 1) void k_recur(const float* Wh_f, const float* Wh_b,
                                                  const int* lengths, float* d_out) {
    int dir = blockIdx.x >> 6;
    int cid = blockIdx.x & 63;
    int j0 = cid * 8;
    const float* Wh = dir ? Wh_b : Wh_f;
    int tid = threadIdx.x;
    int w = tid >> 5, lane = tid & 31;

    __shared__ int   len_s[64];
    __shared__ float part_s[64][128];   // [b][w*16 + group*4 + r]
    __shared__ float c_s[64][8];

    if (tid < 64) len_s[tid] = lengths[tid];
    for (int i = tid; i < 512; i += 256) c_s[i >> 3][i & 7] = 0.f;

    // packed weights: 4 rows x 8 f32x2 per lane
    u64 wq[4][8];
#pragma unroll
    for (int r = 0; r < 4; ++r) {
        int lr = w * 4 + r;
        int grow = (lr >> 3) * 512 + j0 + (lr & 7);
        const ulonglong2* src = (const ulonglong2*)(Wh + (size_t)grow * 512 + lane * 16);
#pragma unroll
        for (int q = 0; q < 4; ++q) {
            ulonglong2 v = src[q];
            wq[r][q * 2] = v.x; wq[r][q * 2 + 1] = v.y;
        }
    }
    __syncthreads();

    float* hbase = &g_h[dir][0][0][0];
    int nact = 64;
    int fb = 0;

    for (int t = 0; t < TT; ++t) {
        while (nact > 0 && len_s[nact - 1] <= t) --nact;
        if (nact == 0) break;
        const float* hr = hbase + (size_t)(t & 1) * (BB * HH);
        float*       hw = hbase + (size_t)((t + 1) & 1) * (BB * HH);

        // prefetch xw gate rows for this thread's 2 (b,col) items (hidden by GEMV)
        float xg[2][4];
#pragma unroll
        for (int rep = 0; rep < 2; ++rep) {
            int it = tid + rep * 256;
            int bb2 = it >> 3, jj = it & 7;
            if (bb2 < nact) {
                const float* xwrow = &g_xw[dir][bb2 * TT + t][0];
                int col = j0 + jj;
                xg[rep][0] = xwrow[col];
                xg[rep][1] = xwrow[512 + col];
                xg[rep][2] = xwrow[1024 + col];
                xg[rep][3] = xwrow[1536 + col];
            }
        }

        // ---- Wh @ h for active batches ----
        {
            const ulonglong2* hp = (const ulonglong2*)hr + lane * 4;
            ulonglong2 p0 = hp[0], p1 = hp[1], p2 = hp[2], p3 = hp[3];
            for (int b = 0; b < nact; ++b) {
                u64 hv[8] = {p0.x, p0.y, p1.x, p1.y, p2.x, p2.y, p3.x, p3.y};
                if (b + 1 < nact) {
                    const ulonglong2* hn = (const ulonglong2*)(hr + (size_t)(b + 1) * 512) + lane * 4;
                    p0 = hn[0]; p1 = hn[1]; p2 = hn[2]; p3 = hn[3];
                }
                u64 a0 = 0ULL, a1 = 0ULL, a2 = 0ULL, a3 = 0ULL;
#pragma unroll
                for (int q = 0; q < 8; ++q) {
                    FMA2(a0, wq[0][q], hv[q]);
                    FMA2(a1, wq[1][q], hv[q]);
                    FMA2(a2, wq[2][q], hv[q]);
                    FMA2(a3, wq[3][q], hv[q]);
                }
                float s0 = HADD2(a0), s1 = HADD2(a1), s2 = HADD2(a2), s3 = HADD2(a3);
#pragma unroll
                for (int off = 16; off >= 4; off >>= 1) {
                    s0 += __shfl_xor_sync(0xffffffffu, s0, off);
                    s1 += __shfl_xor_sync(0xffffffffu, s1, off);
                    s2 += __shfl_xor_sync(0xffffffffu, s2, off);
                    s3 += __shfl_xor_sync(0xffffffffu, s3, off);
                }
                if (lane < 4)
                    *(float4*)&part_s[b][w * 16 + lane * 4] = make_float4(s0, s1, s2, s3);
            }
        }
        __syncthreads();

        // ---- gate math + state update ----
#pragma unroll
        for (int rep = 0; rep < 2; ++rep) {
            int it = tid + rep * 256;
            int b = it >> 3, jj = it & 7;
            int col = j0 + jj;
            float hn;
            if (b < nact) {
                float g[4];
#pragma unroll
                for (int gi = 0; gi < 4; ++gi) {
                    int lr = gi * 8 + jj;
                    int ww = lr >> 2, rr = lr & 3;
                    const float* pp = &part_s[b][ww * 16 + rr];
                    g[gi] = (pp[0] + pp[4]) + (pp[8] + pp[12]) + xg[rep][gi];
                }
                float gi_ = 1.f / (1.f + __expf(-g[0]));
                float gf_ = 1.f / (1.f + __expf(-g[1]));
                float gg_ = tanhf(g[2]);
                float go_ = 1.f / (1.f + __expf(-g[3]));
                float c = gf_ * c_s[b][jj] + gi_ * gg_;
                c_s[b][jj] = c;
                hn = go_ * tanhf(c);
                int tout = dir ? (len_s[b] - 1 - t) : t;
                d_out[((size_t)(b * TT + tout)) * 1024 + (size_t)dir * 512 + col] = hn;
            } else {
                hn = hr[(size_t)b * 512 + col];
            }
            hw[(size_t)b * 512 + col] = hn;
        }
        fb = (t + 1) & 1;

        // ---- inter-CTA step barrier ----
        __threadfence();
        __syncthreads();
        if (tid == 0) {
            atomicAdd(&g_bar[dir], 1u);
            unsigned tgt = (unsigned)(t + 1) * 64u;
            while (*(volatile unsigned*)&g_bar[dir] < tgt) {
                asm volatile("nanosleep.u32 32;");
            }
            __threadfence();
        }
        __syncthreads();
    }

    // ---- final hidden h / c ----
    for (int i = tid; i < 512; i += 256) {
        int b = i >> 3, jj = i & 7;
        int col = j0 + jj;
        float hval = hbase[(size_t)fb * (BB * HH) + (size_t)b * 512 + col];
        d_out[OUT1_O + (size_t)b * 1024 + (size_t)dir * 512 + col] = hval;
        d_out[OUT2_O + (size_t)b * 1024 + (size_t)dir * 512 + col] = c_s[b][jj];
    }
}

// ---------------- launch ----------------
extern "C" void kernel_launch(void* const* d_in, const int* in_sizes, int n_in,
                              void* d_out, int out_size) {
    const void*  act_mask  = d_in[0];
    const int*   act_ids   = (const int*)d_in[1];
    const int*   obs_ids   = (const int*)d_in[2];
    const float* res_feats = (const float*)d_in[3];
    const int*   lengths   = (const int*)d_in[4];
    const float* act_emb   = (const float*)d_in[5];
    const float* obs_emb   = (const float*)d_in[6];
    const float* W_res     = (const float*)d_in[7];
    const float* b_res     = (const float*)d_in[8];
    const float* Wi_f      = (const float*)d_in[9];
    const float* Wh_f      = (const float*)d_in[10];
    const float* bi_f      = (const float*)d_in[11];
    const float* bh_f      = (const float*)d_in[12];
    const float* Wi_b      = (const float*)d_in[13];
    const float* Wh_b      = (const float*)d_in[14];
    const float* bi_b      = (const float*)d_in[15];
    const float* bh_b      = (const float*)d_in[16];

    float* out = (float*)d_out;
    float* emb_out = out + OUT3_O;

    k_sniff<<<1, 256>>>((const unsigned int*)act_mask);
    k_init<<<2048, 256>>>(out);
    k_embed<<<(BB * TT * 64 + 255) / 256, 256>>>(act_mask, act_ids, obs_ids,
                                                 act_emb, obs_emb, emb_out);
    {
        dim3 g(PROJ / 64, (BB * TT) / 128, 1);
        k_res<<<g, 256>>>(res_feats, W_res, b_res, act_mask, emb_out);
    }
    {
        dim3 g(G4 / 128, (BB * TT) / 128, 2);
        k_xw<<<g, 256>>>(emb_out, Wi_f, bi_f, bh_f, Wi_b, bi_b, bh_b, lengths);
    }
    k_recur<<<128, 256>>>(Wh_f, Wh_b, lengths, out);
}

// round 4
// speedup vs baseline: 1.1372x; 1.0357x over previous
#include <cuda_runtime.h>
#include <math.h>

// ---------------- problem constants ----------------
#define BB   64
#define TT   256
#define EMBD 256
#define PROJ 256
#define RDIM 2048
#define HH   512
#define G4   2048
#define DIN  512
#define KOO  3
#define KRR  2

typedef unsigned long long u64;

// output layout (float32): outputs[B,T,2H], hidden_h[1,B,2H], hidden_c[1,B,2H], embedded[B,T,512]
#define OUT0_N  (64ULL*256ULL*1024ULL)
#define OUT1_O  (OUT0_N)
#define OUT2_O  (OUT1_O + 64ULL*1024ULL)
#define OUT3_O  (OUT2_O + 64ULL*1024ULL)

// recurrence dynamic smem: h_s[64][544] + gates[64*32] + c[64*8] + len[64]
#define HROW    544
#define SMEM_RECUR ((64*HROW + 64*32 + 64*8 + 64) * 4)

// ---------------- device scratch ----------------
__device__ __align__(16) float g_xw[2][BB*TT][G4];   // precomputed x@Wi^T + bias per direction
__device__ __align__(16) float g_h[2][2][BB][HH];    // [dir][phase][b][h]
__device__ unsigned int g_bar[2];
__device__ int          g_mask_mode;

// ---------------- f32x2 helpers ----------------
__device__ __forceinline__ void FMA2(u64& acc, u64 a, u64 b) {
    asm("fma.rn.f32x2 %0, %1, %2, %0;" : "+l"(acc) : "l"(a), "l"(b));
}
__device__ __forceinline__ u64 ADD2(u64 a, u64 b) {
    u64 r; asm("add.rn.f32x2 %0, %1, %2;" : "=l"(r) : "l"(a), "l"(b)); return r;
}
__device__ __forceinline__ u64 SPLAT2(float x) {
    u64 r; asm("mov.b64 %0, {%1, %2};" : "=l"(r) : "f"(x), "f"(x)); return r;
}
__device__ __forceinline__ float HADD2(u64 v) {
    float lo, hi; asm("mov.b64 {%0, %1}, %2;" : "=f"(lo), "=f"(hi) : "l"(v)); return lo + hi;
}
__device__ __forceinline__ void UNPACK2(u64 v, float& lo, float& hi) {
    asm("mov.b64 {%0, %1}, %2;" : "=f"(lo), "=f"(hi) : "l"(v));
}

// ---------------- act_mask dtype sniffer ----------------
__global__ void k_sniff(const unsigned int* am) {
    __shared__ int s_mode;
    if (threadIdx.x == 0) s_mode = 0;
    __syncthreads();
    int mode = 0;
    for (int i = threadIdx.x; i < 4096; i += blockDim.x) {
        unsigned v = am[i];
        if (v == 0x3f800000u)      mode = 2;
        else if (v > 1u && mode < 2) mode = 1;
    }
    if (mode) atomicMax(&s_mode, mode);
    __syncthreads();
    if (threadIdx.x == 0) g_mask_mode = s_mode;
}

__device__ __forceinline__ int get_mask(const void* am, int idx) {
    int mode = g_mask_mode;
    if (mode == 1) return ((const unsigned char*)am)[idx] != 0;
    if (mode == 2) return ((const float*)am)[idx] != 0.0f;
    return ((const int*)am)[idx] != 0;
}

// ---------------- init ----------------
__global__ void k_init(float* out0) {
    size_t stride = (size_t)gridDim.x * blockDim.x;
    size_t tid = (size_t)blockIdx.x * blockDim.x + threadIdx.x;
    float4 z = make_float4(0.f, 0.f, 0.f, 0.f);
    float4* o4 = (float4*)out0;
    for (size_t i = tid; i < OUT0_N / 4; i += stride) o4[i] = z;
    float* gh = &g_h[0][0][0][0];
    for (size_t i = tid; i < 2ULL * 2ULL * BB * HH; i += stride) gh[i] = 0.f;
    if (tid < 2) g_bar[tid] = 0u;
}

// ---------------- embedding ----------------
__global__ void k_embed(const void* am, const int* act_ids, const int* obs_ids,
                        const float* act_emb, const float* obs_emb, float* emb_out) {
    int idx = blockIdx.x * blockDim.x + threadIdx.x;
    if (idx >= BB * TT * 64) return;
    int bt = idx >> 6;
    int c4 = (idx & 63) * 4;
    float4 v;
    if (get_mask(am, bt)) {
        int id = act_ids[bt];
        v = *(const float4*)(act_emb + (size_t)id * EMBD + c4);
    } else {
        v = make_float4(0.f, 0.f, 0.f, 0.f);
#pragma unroll
        for (int k = 0; k < KOO; ++k) {
            int id = obs_ids[bt * KOO + k];
            if (id != 0) {
                float4 e = *(const float4*)(obs_emb + (size_t)id * EMBD + c4);
                v.x += e.x; v.y += e.y; v.z += e.z; v.w += e.w;
            }
        }
    }
    *(float4*)(emb_out + (size_t)bt * 512 + c4) = v;
}

// ---------------- res GEMM: BM=64, BN=256 (single n-pass), BK=8, pipelined ----------------
__global__ __launch_bounds__(256) void k_res(const float* feats, const float* W,
                                             const float* b_res, const void* am,
                                             float* emb_out) {
    __shared__ float As[8][64];
    __shared__ float Bs[8][256];
    __shared__ float bias_s[256];
    int m0 = blockIdx.x * 64;
    int tid = threadIdx.x;
    bias_s[tid] = 2.f * b_res[tid];
    int tx = tid & 31, ty = tid >> 5;
    int arow = tid >> 1, acol = (tid & 1) * 4;

    const float* Abase = feats + (size_t)(m0 + arow) * (KRR * RDIM);
    const float* Bbase = W + (size_t)tid * RDIM;

    u64 acc2[4][8];
#pragma unroll
    for (int i = 0; i < 4; ++i)
#pragma unroll
        for (int j = 0; j < 8; ++j) acc2[i][j] = 0ULL;

    float4 a0, a1, bv0, bv1;
    if (tid < 128) {
        a0 = *(const float4*)(Abase + acol);
        a1 = *(const float4*)(Abase + RDIM + acol);
    }
    bv0 = *(const float4*)(Bbase + 0);
    bv1 = *(const float4*)(Bbase + 4);

    for (int k0 = 0; k0 < RDIM; k0 += 8) {
        __syncthreads();
        if (tid < 128) {
            As[acol + 0][arow] = a0.x + a1.x;
            As[acol + 1][arow] = a0.y + a1.y;
            As[acol + 2][arow] = a0.z + a1.z;
            As[acol + 3][arow] = a0.w + a1.w;
        }
        Bs[0][tid] = bv0.x; Bs[1][tid] = bv0.y; Bs[2][tid] = bv0.z; Bs[3][tid] = bv0.w;
        Bs[4][tid] = bv1.x; Bs[5][tid] = bv1.y; Bs[6][tid] = bv1.z; Bs[7][tid] = bv1.w;
        __syncthreads();
        if (k0 + 8 < RDIM) {
            if (tid < 128) {
                a0 = *(const float4*)(Abase + k0 + 8 + acol);
                a1 = *(const float4*)(Abase + RDIM + k0 + 8 + acol);
            }
            bv0 = *(const float4*)(Bbase + k0 + 8);
            bv1 = *(const float4*)(Bbase + k0 + 12);
        }
#pragma unroll
        for (int kk = 0; kk < 8; ++kk) {
            const ulonglong2* pA = (const ulonglong2*)&As[kk][ty * 8];
            ulonglong2 qa0 = pA[0], qa1 = pA[1];
            u64 ra[4] = {qa0.x, qa0.y, qa1.x, qa1.y};
            float4 n0v = *(float4*)&Bs[kk][tx * 8];
            float4 n1v = *(float4*)&Bs[kk][tx * 8 + 4];
            u64 rb[8] = {SPLAT2(n0v.x), SPLAT2(n0v.y), SPLAT2(n0v.z), SPLAT2(n0v.w),
                         SPLAT2(n1v.x), SPLAT2(n1v.y), SPLAT2(n1v.z), SPLAT2(n1v.w)};
#pragma unroll
            for (int i = 0; i < 4; ++i)
#pragma unroll
                for (int j = 0; j < 8; ++j) FMA2(acc2[i][j], ra[i], rb[j]);
        }
    }
#pragma unroll
    for (int i2 = 0; i2 < 4; ++i2) {
        int me = m0 + ty * 8 + i2 * 2;
        int msk_e = get_mask(am, me);
        int msk_o = get_mask(am, me + 1);
        float* oe = emb_out + (size_t)me * 512 + 256;
        float* oo = oe + 512;
#pragma unroll
        for (int j = 0; j < 8; ++j) {
            int n = tx * 8 + j;
            float lo, hi; UNPACK2(acc2[i2][j], lo, hi);
            oe[n] = msk_e ? 0.f : (lo + bias_s[n]);
            oo[n] = msk_o ? 0.f : (hi + bias_s[n]);
        }
    }
}

// ---------------- xw GEMM: BM=128, BN=128, BK=8, pipelined ----------------
__global__ __launch_bounds__(256) void k_xw(const float* emb,
                                            const float* Wi_f, const float* bi_f, const float* bh_f,
                                            const float* Wi_b, const float* bi_b, const float* bh_b,
                                            const int* lengths) {
    int dir = blockIdx.z;
    const float* Wi = dir ? Wi_b : Wi_f;
    const float* bi = dir ? bi_b : bi_f;
    const float* bh = dir ? bh_b : bh_f;
    int m0 = blockIdx.y * 128;
    int n0 = blockIdx.x * 128;
    int b = m0 >> 8;
    int s0 = m0 & 255;
    int lenb = lengths[b];
    if (s0 >= lenb) return;

    __shared__ float As[8][128];
    __shared__ float Bs[8][128];
    __shared__ float bias_s[128];
    int tid = threadIdx.x;
    if (tid < 128) bias_s[tid] = bi[n0 + tid] + bh[n0 + tid];
    int arow = tid >> 1, acol = (tid & 1) * 4;
    int tx = tid & 15, ty = tid >> 4;

    int s = s0 + arow;
    int t = dir ? (lenb - 1 - s) : s;
    if (t < 0) t = 0;
    const float* Arow = emb + ((size_t)(b * TT + t)) * 512;
    const float* Brow = Wi + (size_t)(n0 + arow) * 512;

    u64 acc2[4][8];
#pragma unroll
    for (int i = 0; i < 4; ++i)
#pragma unroll
        for (int j = 0; j < 8; ++j) acc2[i][j] = 0ULL;

    float4 av = *(const float4*)(Arow + acol);
    float4 bv = *(const float4*)(Brow + acol);

    for (int k0 = 0; k0 < 512; k0 += 8) {
        __syncthreads();
        As[acol + 0][arow] = av.x; As[acol + 1][arow] = av.y;
        As[acol + 2][arow] = av.z; As[acol + 3][arow] = av.w;
        Bs[acol + 0][arow] = bv.x; Bs[acol + 1][arow] = bv.y;
        Bs[acol + 2][arow] = bv.z; Bs[acol + 3][arow] = bv.w;
        __syncthreads();
        if (k0 + 8 < 512) {
            av = *(const float4*)(Arow + k0 + 8 + acol);
            bv = *(const float4*)(Brow + k0 + 8 + acol);
        }
#pragma unroll
        for (int kk = 0; kk < 8; ++kk) {
            const ulonglong2* pA = (const ulonglong2*)&As[kk][ty * 8];
            ulonglong2 qa0 = pA[0], qa1 = pA[1];
            u64 ra[4] = {qa0.x, qa0.y, qa1.x, qa1.y};
            float4 b0v = *(float4*)&Bs[kk][tx * 8];
            float4 b1v = *(float4*)&Bs[kk][tx * 8 + 4];
            u64 rb[8] = {SPLAT2(b0v.x), SPLAT2(b0v.y), SPLAT2(b0v.z), SPLAT2(b0v.w),
                         SPLAT2(b1v.x), SPLAT2(b1v.y), SPLAT2(b1v.z), SPLAT2(b1v.w)};
#pragma unroll
            for (int i = 0; i < 4; ++i)
#pragma unroll
                for (int j = 0; j < 8; ++j) FMA2(acc2[i][j], ra[i], rb[j]);
        }
    }
#pragma unroll
    for (int i2 = 0; i2 < 4; ++i2) {
        int me = m0 + ty * 8 + i2 * 2;
        float* oe = &g_xw[dir][me][0];
        float* oo = &g_xw[dir][me + 1][0];
#pragma unroll
        for (int j = 0; j < 8; ++j) {
            int n = tx * 8 + j;
            float lo, hi; UNPACK2(acc2[i2][j], lo, hi);
            float bb = bias_s[n];
            oe[n0 + n] = lo + bb;
            oo[n0 + n] = hi + bb;
        }
    }
}

// ---------------- persistent recurrence v3: smem h staging, conflict-free layout ----------------
// 128 CTAs: [0,64)=fwd, [64,128)=bwd. CTA owns 8 h-cols (32 gate rows).
// Lane layout: lane = r*8+kq. Thread owns 1 gate row (lr=w*4+r) x 64 k (slice kq).
// h staged in smem with 68-float slice padding -> conflict-free LDS + 4-way broadcast.
__global__ __launch_bounds__(256, 1) void k_recur(const float* Wh_f, const float* Wh_b,
                                                  const int* lengths, float* d_out) {
    extern __shared__ float sm_f[];
    float* h_s     = sm_f;                     // 64 * 544
    float* gates_s = sm_f + 64 * HROW;         // 64 * 32
    float* c_s     = gates_s + 64 * 32;        // 64 * 8
    int*   len_s   = (int*)(c_s + 64 * 8);     // 64

    int dir = blockIdx.x >> 6;
    int cid = blockIdx.x & 63;
    int j0 = cid * 8;
    const float* Wh = dir ? Wh_b : Wh_f;
    int tid = threadIdx.x;
    int w = tid >> 5, lane = tid & 31;
    int r = lane >> 3, kq = lane & 7;
    int lr = w * 4 + r;

    if (tid < 64) len_s[tid] = lengths[tid];
    for (int i = tid; i < 512; i += 256) c_s[i] = 0.f;

    // weights: one gate row, 64 k per thread = 32 u64
    u64 wq[32];
    {
        int grow = (lr >> 3) * 512 + j0 + (lr & 7);
        const ulonglong2* wsrc = (const ulonglong2*)(Wh + (size_t)grow * 512 + kq * 64);
#pragma unroll
        for (int q = 0; q < 16; ++q) {
            ulonglong2 v = wsrc[q];
            wq[2 * q] = v.x; wq[2 * q + 1] = v.y;
        }
    }
    __syncthreads();

    float* hbase = &g_h[dir][0][0][0];
    int nact = 64, pnact = 64;
    int fb = 0;

    for (int t = 0; t < TT; ++t) {
        while (nact > 0 && len_s[nact - 1] <= t) --nact;
        if (nact == 0) break;
        const float* hr = hbase + (size_t)(t & 1) * (BB * HH);
        float*       hw = hbase + (size_t)((t + 1) & 1) * (BB * HH);

        // prefetch xw gate rows (LDG latency overlaps staging)
        float xg[2][4];
#pragma unroll
        for (int rep = 0; rep < 2; ++rep) {
            int it = tid + rep * 256;
            int bb2 = it >> 3, jj = it & 7;
            if (bb2 < nact) {
                const float* xwrow = &g_xw[dir][bb2 * TT + t][0];
                int col = j0 + jj;
                xg[rep][0] = xwrow[col];
                xg[rep][1] = xwrow[512 + col];
                xg[rep][2] = xwrow[1024 + col];
                xg[rep][3] = xwrow[1536 + col];
            }
        }

        // ---- stage h into smem (padded layout) ----
        {
            const float4* hr4 = (const float4*)hr;
            float4* hs4 = (float4*)h_s;
            int n4 = nact * 128;
            for (int i = tid; i < n4; i += 256) {
                int bb2 = i >> 7, q4 = i & 127;
                hs4[bb2 * (HROW / 4) + (q4 >> 4) * 17 + (q4 & 15)] = hr4[i];
            }
        }
        __syncthreads();

        // ---- Wh @ h from smem ----
#pragma unroll 2
        for (int b = 0; b < nact; ++b) {
            const ulonglong2* hp = (const ulonglong2*)(h_s + b * HROW + kq * 68);
            u64 a0 = 0ULL, a1 = 0ULL, a2 = 0ULL, a3 = 0ULL;
#pragma unroll
            for (int q = 0; q < 4; ++q) {
                ulonglong2 v0 = hp[q * 4 + 0];
                ulonglong2 v1 = hp[q * 4 + 1];
                ulonglong2 v2 = hp[q * 4 + 2];
                ulonglong2 v3 = hp[q * 4 + 3];
                FMA2(a0, wq[q * 8 + 0], v0.x); FMA2(a1, wq[q * 8 + 1], v0.y);
                FMA2(a2, wq[q * 8 + 2], v1.x); FMA2(a3, wq[q * 8 + 3], v1.y);
                FMA2(a0, wq[q * 8 + 4], v2.x); FMA2(a1, wq[q * 8 + 5], v2.y);
                FMA2(a2, wq[q * 8 + 6], v3.x); FMA2(a3, wq[q * 8 + 7], v3.y);
            }
            float s = HADD2(ADD2(ADD2(a0, a1), ADD2(a2, a3)));
            s += __shfl_xor_sync(0xffffffffu, s, 1);
            s += __shfl_xor_sync(0xffffffffu, s, 2);
            s += __shfl_xor_sync(0xffffffffu, s, 4);
            if (kq == 0) gates_s[b * 32 + lr] = s;
        }
        __syncthreads();

        // ---- gate math + state update (active batches) ----
#pragma unroll
        for (int rep = 0; rep < 2; ++rep) {
            int it = tid + rep * 256;
            int b = it >> 3, jj = it & 7;
            if (b < nact) {
                int col = j0 + jj;
                float gi = gates_s[b * 32 + jj]      + xg[rep][0];
                float gf = gates_s[b * 32 + 8 + jj]  + xg[rep][1];
                float gg = gates_s[b * 32 + 16 + jj] + xg[rep][2];
                float go = gates_s[b * 32 + 24 + jj] + xg[rep][3];
                gi = 1.f / (1.f + __expf(-gi));
                gf = 1.f / (1.f + __expf(-gf));
                gg = tanhf(gg);
                go = 1.f / (1.f + __expf(-go));
                float c = gf * c_s[b * 8 + jj] + gi * gg;
                c_s[b * 8 + jj] = c;
                float hn = go * tanhf(c);
                int tout = dir ? (len_s[b] - 1 - t) : t;
                d_out[((size_t)(b * TT + tout)) * 1024 + (size_t)dir * 512 + col] = hn;
                hw[(size_t)b * 512 + col] = hn;
            }
        }
        // ---- copy just-frozen rows once (own 8 cols) ----
        {
            int nfroz = pnact - nact;
            if (tid < nfroz * 8) {
                int b = nact + (tid >> 3), jj = tid & 7;
                int col = j0 + jj;
                hw[(size_t)b * 512 + col] = hr[(size_t)b * 512 + col];
            }
        }
        pnact = nact;
        fb = (t + 1) & 1;

        // ---- inter-CTA step barrier ----
        __threadfence();
        __syncthreads();
        if (tid == 0) {
            atomicAdd(&g_bar[dir], 1u);
            unsigned tgt = (unsigned)(t + 1) * 64u;
            while (*(volatile unsigned*)&g_bar[dir] < tgt) {
                asm volatile("nanosleep.u32 32;");
            }
            __threadfence();
        }
        __syncthreads();
    }

    // ---- final hidden h / c ----
    for (int i = tid; i < 512; i += 256) {
        int b = i >> 3, jj = i & 7;
        int col = j0 + jj;
        float hval = hbase[(size_t)fb * (BB * HH) + (size_t)b * 512 + col];
        d_out[OUT1_O + (size_t)b * 1024 + (size_t)dir * 512 + col] = hval;
        d_out[OUT2_O + (size_t)b * 1024 + (size_t)dir * 512 + col] = c_s[b * 8 + jj];
    }
}

// ---------------- launch ----------------
extern "C" void kernel_launch(void* const* d_in, const int* in_sizes, int n_in,
                              void* d_out, int out_size) {
    const void*  act_mask  = d_in[0];
    const int*   act_ids   = (const int*)d_in[1];
    const int*   obs_ids   = (const int*)d_in[2];
    const float* res_feats = (const float*)d_in[3];
    const int*   lengths   = (const int*)d_in[4];
    const float* act_emb   = (const float*)d_in[5];
    const float* obs_emb   = (const float*)d_in[6];
    const float* W_res     = (const float*)d_in[7];
    const float* b_res     = (const float*)d_in[8];
    const float* Wi_f      = (const float*)d_in[9];
    const float* Wh_f      = (const float*)d_in[10];
    const float* bi_f      = (const float*)d_in[11];
    const float* bh_f      = (const float*)d_in[12];
    const float* Wi_b      = (const float*)d_in[13];
    const float* Wh_b      = (const float*)d_in[14];
    const float* bi_b      = (const float*)d_in[15];
    const float* bh_b      = (const float*)d_in[16];

    float* out = (float*)d_out;
    float* emb_out = out + OUT3_O;

    cudaFuncSetAttribute(k_recur, cudaFuncAttributeMaxDynamicSharedMemorySize, SMEM_RECUR);

    k_sniff<<<1, 256>>>((const unsigned int*)act_mask);
    k_init<<<2048, 256>>>(out);
    k_embed<<<(BB * TT * 64 + 255) / 256, 256>>>(act_mask, act_ids, obs_ids,
                                                 act_emb, obs_emb, emb_out);
    k_res<<<(BB * TT) / 64, 256>>>(res_feats, W_res, b_res, act_mask, emb_out);
    {
        dim3 g(G4 / 128, (BB * TT) / 128, 2);
        k_xw<<<g, 256>>>(emb_out, Wi_f, bi_f, bh_f, Wi_b, bi_b, bh_b, lengths);
    }
    k_recur<<<128, 256, SMEM_RECUR>>>(Wh_f, Wh_b, lengths, out);
}

// round 5
// speedup vs baseline: 1.1651x; 1.0246x over previous
#include <cuda_runtime.h>
#include <math.h>

// ---------------- problem constants ----------------
#define BB   64
#define TT   256
#define EMBD 256
#define PROJ 256
#define RDIM 2048
#define HH   512
#define G4   2048
#define DIN  512
#define KOO  3
#define KRR  2

typedef unsigned long long u64;

// output layout (float32): outputs[B,T,2H], hidden_h[1,B,2H], hidden_c[1,B,2H], embedded[B,T,512]
#define OUT0_N  (64ULL*256ULL*1024ULL)
#define OUT1_O  (OUT0_N)
#define OUT2_O  (OUT1_O + 64ULL*1024ULL)
#define OUT3_O  (OUT2_O + 64ULL*1024ULL)

// recurrence dynamic smem: h_s[64][544] + gates[64*32] + c[64*8] + len[64]
#define HROW    544
#define SMEM_RECUR ((64*HROW + 64*32 + 64*8 + 64) * 4)

// ---------------- device scratch ----------------
__device__ __align__(16) float g_xw[2][BB*TT][G4];   // precomputed x@Wi^T + bias per direction
__device__ __align__(16) float g_h[2][2][BB][HH];    // [dir][phase][b][h]
__device__ unsigned int g_bar[2];
__device__ int          g_mask_mode;

// ---------------- f32x2 helpers ----------------
__device__ __forceinline__ void FMA2(u64& acc, u64 a, u64 b) {
    asm("fma.rn.f32x2 %0, %1, %2, %0;" : "+l"(acc) : "l"(a), "l"(b));
}
__device__ __forceinline__ u64 ADD2(u64 a, u64 b) {
    u64 r; asm("add.rn.f32x2 %0, %1, %2;" : "=l"(r) : "l"(a), "l"(b)); return r;
}
__device__ __forceinline__ u64 SPLAT2(float x) {
    u64 r; asm("mov.b64 %0, {%1, %2};" : "=l"(r) : "f"(x), "f"(x)); return r;
}
__device__ __forceinline__ float HADD2(u64 v) {
    float lo, hi; asm("mov.b64 {%0, %1}, %2;" : "=f"(lo), "=f"(hi) : "l"(v)); return lo + hi;
}
__device__ __forceinline__ void UNPACK2(u64 v, float& lo, float& hi) {
    asm("mov.b64 {%0, %1}, %2;" : "=f"(lo), "=f"(hi) : "l"(v));
}
__device__ __forceinline__ unsigned LD_ACQ(const unsigned* p) {
    unsigned v;
    asm volatile("ld.acquire.gpu.global.u32 %0, [%1];" : "=r"(v) : "l"(p) : "memory");
    return v;
}

// ---------------- act_mask dtype sniffer ----------------
__global__ void k_sniff(const unsigned int* am) {
    __shared__ int s_mode;
    if (threadIdx.x == 0) s_mode = 0;
    __syncthreads();
    int mode = 0;
    for (int i = threadIdx.x; i < 4096; i += blockDim.x) {
        unsigned v = am[i];
        if (v == 0x3f800000u)      mode = 2;
        else if (v > 1u && mode < 2) mode = 1;
    }
    if (mode) atomicMax(&s_mode, mode);
    __syncthreads();
    if (threadIdx.x == 0) g_mask_mode = s_mode;
}

__device__ __forceinline__ int get_mask(const void* am, int idx) {
    int mode = g_mask_mode;
    if (mode == 1) return ((const unsigned char*)am)[idx] != 0;
    if (mode == 2) return ((const float*)am)[idx] != 0.0f;
    return ((const int*)am)[idx] != 0;
}

// ---------------- init ----------------
__global__ void k_init(float* out0) {
    size_t stride = (size_t)gridDim.x * blockDim.x;
    size_t tid = (size_t)blockIdx.x * blockDim.x + threadIdx.x;
    float4 z = make_float4(0.f, 0.f, 0.f, 0.f);
    float4* o4 = (float4*)out0;
    for (size_t i = tid; i < OUT0_N / 4; i += stride) o4[i] = z;
    float* gh = &g_h[0][0][0][0];
    for (size_t i = tid; i < 2ULL * 2ULL * BB * HH; i += stride) gh[i] = 0.f;
    if (tid < 2) g_bar[tid] = 0u;
}

// ---------------- embedding ----------------
__global__ void k_embed(const void* am, const int* act_ids, const int* obs_ids,
                        const float* act_emb, const float* obs_emb, float* emb_out) {
    int idx = blockIdx.x * blockDim.x + threadIdx.x;
    if (idx >= BB * TT * 64) return;
    int bt = idx >> 6;
    int c4 = (idx & 63) * 4;
    float4 v;
    if (get_mask(am, bt)) {
        int id = act_ids[bt];
        v = *(const float4*)(act_emb + (size_t)id * EMBD + c4);
    } else {
        v = make_float4(0.f, 0.f, 0.f, 0.f);
#pragma unroll
        for (int k = 0; k < KOO; ++k) {
            int id = obs_ids[bt * KOO + k];
            if (id != 0) {
                float4 e = *(const float4*)(obs_emb + (size_t)id * EMBD + c4);
                v.x += e.x; v.y += e.y; v.z += e.z; v.w += e.w;
            }
        }
    }
    *(float4*)(emb_out + (size_t)bt * 512 + c4) = v;
}

// ---------------- res GEMM: BM=64, BN=256 (single n-pass), BK=8, pipelined ----------------
__global__ __launch_bounds__(256) void k_res(const float* feats, const float* W,
                                             const float* b_res, const void* am,
                                             float* emb_out) {
    __shared__ float As[8][64];
    __shared__ float Bs[8][256];
    __shared__ float bias_s[256];
    int m0 = blockIdx.x * 64;
    int tid = threadIdx.x;
    bias_s[tid] = 2.f * b_res[tid];
    int tx = tid & 31, ty = tid >> 5;
    int arow = tid >> 1, acol = (tid & 1) * 4;

    const float* Abase = feats + (size_t)(m0 + arow) * (KRR * RDIM);
    const float* Bbase = W + (size_t)tid * RDIM;

    u64 acc2[4][8];
#pragma unroll
    for (int i = 0; i < 4; ++i)
#pragma unroll
        for (int j = 0; j < 8; ++j) acc2[i][j] = 0ULL;

    float4 a0, a1, bv0, bv1;
    if (tid < 128) {
        a0 = *(const float4*)(Abase + acol);
        a1 = *(const float4*)(Abase + RDIM + acol);
    }
    bv0 = *(const float4*)(Bbase + 0);
    bv1 = *(const float4*)(Bbase + 4);

    for (int k0 = 0; k0 < RDIM; k0 += 8) {
        __syncthreads();
        if (tid < 128) {
            As[acol + 0][arow] = a0.x + a1.x;
            As[acol + 1][arow] = a0.y + a1.y;
            As[acol + 2][arow] = a0.z + a1.z;
            As[acol + 3][arow] = a0.w + a1.w;
        }
        Bs[0][tid] = bv0.x; Bs[1][tid] = bv0.y; Bs[2][tid] = bv0.z; Bs[3][tid] = bv0.w;
        Bs[4][tid] = bv1.x; Bs[5][tid] = bv1.y; Bs[6][tid] = bv1.z; Bs[7][tid] = bv1.w;
        __syncthreads();
        if (k0 + 8 < RDIM) {
            if (tid < 128) {
                a0 = *(const float4*)(Abase + k0 + 8 + acol);
                a1 = *(const float4*)(Abase + RDIM + k0 + 8 + acol);
            }
            bv0 = *(const float4*)(Bbase + k0 + 8);
            bv1 = *(const float4*)(Bbase + k0 + 12);
        }
#pragma unroll
        for (int kk = 0; kk < 8; ++kk) {
            const ulonglong2* pA = (const ulonglong2*)&As[kk][ty * 8];
            ulonglong2 qa0 = pA[0], qa1 = pA[1];
            u64 ra[4] = {qa0.x, qa0.y, qa1.x, qa1.y};
            float4 n0v = *(float4*)&Bs[kk][tx * 8];
            float4 n1v = *(float4*)&Bs[kk][tx * 8 + 4];
            u64 rb[8] = {SPLAT2(n0v.x), SPLAT2(n0v.y), SPLAT2(n0v.z), SPLAT2(n0v.w),
                         SPLAT2(n1v.x), SPLAT2(n1v.y), SPLAT2(n1v.z), SPLAT2(n1v.w)};
#pragma unroll
            for (int i = 0; i < 4; ++i)
#pragma unroll
                for (int j = 0; j < 8; ++j) FMA2(acc2[i][j], ra[i], rb[j]);
        }
    }
#pragma unroll
    for (int i2 = 0; i2 < 4; ++i2) {
        int me = m0 + ty * 8 + i2 * 2;
        int msk_e = get_mask(am, me);
        int msk_o = get_mask(am, me + 1);
        float* oe = emb_out + (size_t)me * 512 + 256;
        float* oo = oe + 512;
#pragma unroll
        for (int j = 0; j < 8; ++j) {
            int n = tx * 8 + j;
            float lo, hi; UNPACK2(acc2[i2][j], lo, hi);
            oe[n] = msk_e ? 0.f : (lo + bias_s[n]);
            oo[n] = msk_o ? 0.f : (hi + bias_s[n]);
        }
    }
}

// ---------------- xw GEMM: BM=128, BN=128, BK=8, pipelined ----------------
__global__ __launch_bounds__(256) void k_xw(const float* emb,
                                            const float* Wi_f, const float* bi_f, const float* bh_f,
                                            const float* Wi_b, const float* bi_b, const float* bh_b,
                                            const int* lengths) {
    int dir = blockIdx.z;
    const float* Wi = dir ? Wi_b : Wi_f;
    const float* bi = dir ? bi_b : bi_f;
    const float* bh = dir ? bh_b : bh_f;
    int m0 = blockIdx.y * 128;
    int n0 = blockIdx.x * 128;
    int b = m0 >> 8;
    int s0 = m0 & 255;
    int lenb = lengths[b];
    if (s0 >= lenb) return;

    __shared__ float As[8][128];
    __shared__ float Bs[8][128];
    __shared__ float bias_s[128];
    int tid = threadIdx.x;
    if (tid < 128) bias_s[tid] = bi[n0 + tid] + bh[n0 + tid];
    int arow = tid >> 1, acol = (tid & 1) * 4;
    int tx = tid & 15, ty = tid >> 4;

    int s = s0 + arow;
    int t = dir ? (lenb - 1 - s) : s;
    if (t < 0) t = 0;
    const float* Arow = emb + ((size_t)(b * TT + t)) * 512;
    const float* Brow = Wi + (size_t)(n0 + arow) * 512;

    u64 acc2[4][8];
#pragma unroll
    for (int i = 0; i < 4; ++i)
#pragma unroll
        for (int j = 0; j < 8; ++j) acc2[i][j] = 0ULL;

    float4 av = *(const float4*)(Arow + acol);
    float4 bv = *(const float4*)(Brow + acol);

    for (int k0 = 0; k0 < 512; k0 += 8) {
        __syncthreads();
        As[acol + 0][arow] = av.x; As[acol + 1][arow] = av.y;
        As[acol + 2][arow] = av.z; As[acol + 3][arow] = av.w;
        Bs[acol + 0][arow] = bv.x; Bs[acol + 1][arow] = bv.y;
        Bs[acol + 2][arow] = bv.z; Bs[acol + 3][arow] = bv.w;
        __syncthreads();
        if (k0 + 8 < 512) {
            av = *(const float4*)(Arow + k0 + 8 + acol);
            bv = *(const float4*)(Brow + k0 + 8 + acol);
        }
#pragma unroll
        for (int kk = 0; kk < 8; ++kk) {
            const ulonglong2* pA = (const ulonglong2*)&As[kk][ty * 8];
            ulonglong2 qa0 = pA[0], qa1 = pA[1];
            u64 ra[4] = {qa0.x, qa0.y, qa1.x, qa1.y};
            float4 b0v = *(float4*)&Bs[kk][tx * 8];
            float4 b1v = *(float4*)&Bs[kk][tx * 8 + 4];
            u64 rb[8] = {SPLAT2(b0v.x), SPLAT2(b0v.y), SPLAT2(b0v.z), SPLAT2(b0v.w),
                         SPLAT2(b1v.x), SPLAT2(b1v.y), SPLAT2(b1v.z), SPLAT2(b1v.w)};
#pragma unroll
            for (int i = 0; i < 4; ++i)
#pragma unroll
                for (int j = 0; j < 8; ++j) FMA2(acc2[i][j], ra[i], rb[j]);
        }
    }
#pragma unroll
    for (int i2 = 0; i2 < 4; ++i2) {
        int me = m0 + ty * 8 + i2 * 2;
        float* oe = &g_xw[dir][me][0];
        float* oo = &g_xw[dir][me + 1][0];
#pragma unroll
        for (int j = 0; j < 8; ++j) {
            int n = tx * 8 + j;
            float lo, hi; UNPACK2(acc2[i2][j], lo, hi);
            float bb = bias_s[n];
            oe[n0 + n] = lo + bb;
            oo[n0 + n] = hi + bb;
        }
    }
}

// ---------------- persistent recurrence v4: fast acquire-barrier + hidden xg prefetch ----------------
// 128 CTAs: [0,64)=fwd, [64,128)=bwd. CTA owns 8 h-cols (32 gate rows).
// Lane layout: lane = r*8+kq. Thread owns 1 gate row (lr=w*4+r) x 64 k (slice kq).
__global__ __launch_bounds__(256, 1) void k_recur(const float* Wh_f, const float* Wh_b,
                                                  const int* lengths, float* d_out) {
    extern __shared__ float sm_f[];
    float* h_s     = sm_f;                     // 64 * 544
    float* gates_s = sm_f + 64 * HROW;         // 64 * 32
    float* c_s     = gates_s + 64 * 32;        // 64 * 8
    int*   len_s   = (int*)(c_s + 64 * 8);     // 64

    int dir = blockIdx.x >> 6;
    int cid = blockIdx.x & 63;
    int j0 = cid * 8;
    const float* Wh = dir ? Wh_b : Wh_f;
    int tid = threadIdx.x;
    int w = tid >> 5, lane = tid & 31;
    int r = lane >> 3, kq = lane & 7;
    int lr = w * 4 + r;

    if (tid < 64) len_s[tid] = lengths[tid];
    for (int i = tid; i < 512; i += 256) c_s[i] = 0.f;

    // weights: one gate row, 64 k per thread = 32 u64
    u64 wq[32];
    {
        int grow = (lr >> 3) * 512 + j0 + (lr & 7);
        const ulonglong2* wsrc = (const ulonglong2*)(Wh + (size_t)grow * 512 + kq * 64);
#pragma unroll
        for (int q = 0; q < 16; ++q) {
            ulonglong2 v = wsrc[q];
            wq[2 * q] = v.x; wq[2 * q + 1] = v.y;
        }
    }
    __syncthreads();

    float* hbase = &g_h[dir][0][0][0];
    unsigned* bar = &g_bar[dir];
    int nact = 64, pnact = 64;      // len >= 1 always -> nact(0) = 64
    int fb = 0;

    // prefetch xg for t=0
    float xg[2][4];
#pragma unroll
    for (int rep = 0; rep < 2; ++rep) {
        int it = tid + rep * 256;
        int bb2 = it >> 3, jj = it & 7;
        const float* xwrow = &g_xw[dir][bb2 * TT + 0][0];
        int col = j0 + jj;
        xg[rep][0] = xwrow[col];
        xg[rep][1] = xwrow[512 + col];
        xg[rep][2] = xwrow[1024 + col];
        xg[rep][3] = xwrow[1536 + col];
    }

    for (int t = 0; t < TT; ++t) {
        if (nact == 0) break;
        const float* hr = hbase + (size_t)(t & 1) * (BB * HH);
        float*       hw = hbase + (size_t)((t + 1) & 1) * (BB * HH);

        // ---- stage h into smem (padded layout) ----
        {
            const float4* hr4 = (const float4*)hr;
            float4* hs4 = (float4*)h_s;
            int n4 = nact * 128;
            for (int i = tid; i < n4; i += 256) {
                int bb2 = i >> 7, q4 = i & 127;
                hs4[bb2 * (HROW / 4) + (q4 >> 4) * 17 + (q4 & 15)] = hr4[i];
            }
        }
        __syncthreads();

        // ---- Wh @ h from smem ----
#pragma unroll 2
        for (int b = 0; b < nact; ++b) {
            const ulonglong2* hp = (const ulonglong2*)(h_s + b * HROW + kq * 68);
            u64 a0 = 0ULL, a1 = 0ULL, a2 = 0ULL, a3 = 0ULL;
#pragma unroll
            for (int q = 0; q < 4; ++q) {
                ulonglong2 v0 = hp[q * 4 + 0];
                ulonglong2 v1 = hp[q * 4 + 1];
                ulonglong2 v2 = hp[q * 4 + 2];
                ulonglong2 v3 = hp[q * 4 + 3];
                FMA2(a0, wq[q * 8 + 0], v0.x); FMA2(a1, wq[q * 8 + 1], v0.y);
                FMA2(a2, wq[q * 8 + 2], v1.x); FMA2(a3, wq[q * 8 + 3], v1.y);
                FMA2(a0, wq[q * 8 + 4], v2.x); FMA2(a1, wq[q * 8 + 5], v2.y);
                FMA2(a2, wq[q * 8 + 6], v3.x); FMA2(a3, wq[q * 8 + 7], v3.y);
            }
            float s = HADD2(ADD2(ADD2(a0, a1), ADD2(a2, a3)));
            s += __shfl_xor_sync(0xffffffffu, s, 1);
            s += __shfl_xor_sync(0xffffffffu, s, 2);
            s += __shfl_xor_sync(0xffffffffu, s, 4);
            if (kq == 0) gates_s[b * 32 + lr] = s;
        }
        __syncthreads();

        // ---- gate math + state update (active batches) ----
#pragma unroll
        for (int rep = 0; rep < 2; ++rep) {
            int it = tid + rep * 256;
            int b = it >> 3, jj = it & 7;
            if (b < nact) {
                int col = j0 + jj;
                float gi = gates_s[b * 32 + jj]      + xg[rep][0];
                float gf = gates_s[b * 32 + 8 + jj]  + xg[rep][1];
                float gg = gates_s[b * 32 + 16 + jj] + xg[rep][2];
                float go = gates_s[b * 32 + 24 + jj] + xg[rep][3];
                gi = 1.f / (1.f + __expf(-gi));
                gf = 1.f / (1.f + __expf(-gf));
                gg = tanhf(gg);
                go = 1.f / (1.f + __expf(-go));
                float c = gf * c_s[b * 8 + jj] + gi * gg;
                c_s[b * 8 + jj] = c;
                float hn = go * tanhf(c);
                int tout = dir ? (len_s[b] - 1 - t) : t;
                d_out[((size_t)(b * TT + tout)) * 1024 + (size_t)dir * 512 + col] = hn;
                hw[(size_t)b * 512 + col] = hn;
            }
        }
        // ---- copy just-frozen rows once (own 8 cols) ----
        {
            int nfroz = pnact - nact;
            if (tid < nfroz * 8) {
                int b = nact + (tid >> 3), jj = tid & 7;
                int col = j0 + jj;
                hw[(size_t)b * 512 + col] = hr[(size_t)b * 512 + col];
            }
        }
        pnact = nact;
        fb = (t + 1) & 1;

        // ---- inter-CTA step barrier: release-arrive, prefetch, acquire-poll ----
        __threadfence();
        __syncthreads();
        if (tid == 0) atomicAdd(bar, 1u);

        // nact for t+1, computed locally; prefetch next xg under the barrier wait
        int nn = nact;
        while (nn > 0 && len_s[nn - 1] <= t + 1) --nn;
#pragma unroll
        for (int rep = 0; rep < 2; ++rep) {
            int it = tid + rep * 256;
            int bb2 = it >> 3, jj = it & 7;
            if (bb2 < nn) {
                const float* xwrow = &g_xw[dir][bb2 * TT + (t + 1)][0];
                int col = j0 + jj;
                xg[rep][0] = xwrow[col];
                xg[rep][1] = xwrow[512 + col];
                xg[rep][2] = xwrow[1024 + col];
                xg[rep][3] = xwrow[1536 + col];
            }
        }

        if (tid == 0) {
            unsigned tgt = (unsigned)(t + 1) * 64u;
            while (LD_ACQ(bar) < tgt) { }
        }
        __syncthreads();
        nact = nn;
    }

    // ---- final hidden h / c ----
    for (int i = tid; i < 512; i += 256) {
        int b = i >> 3, jj = i & 7;
        int col = j0 + jj;
        float hval = hbase[(size_t)fb * (BB * HH) + (size_t)b * 512 + col];
        d_out[OUT1_O + (size_t)b * 1024 + (size_t)dir * 512 + col] = hval;
        d_out[OUT2_O + (size_t)b * 1024 + (size_t)dir * 512 + col] = c_s[b * 8 + jj];
    }
}

// ---------------- launch ----------------
extern "C" void kernel_launch(void* const* d_in, const int* in_sizes, int n_in,
                              void* d_out, int out_size) {
    const void*  act_mask  = d_in[0];
    const int*   act_ids   = (const int*)d_in[1];
    const int*   obs_ids   = (const int*)d_in[2];
    const float* res_feats = (const float*)d_in[3];
    const int*   lengths   = (const int*)d_in[4];
    const float* act_emb   = (const float*)d_in[5];
    const float* obs_emb   = (const float*)d_in[6];
    const float* W_res     = (const float*)d_in[7];
    const float* b_res     = (const float*)d_in[8];
    const float* Wi_f      = (const float*)d_in[9];
    const float* Wh_f      = (const float*)d_in[10];
    const float* bi_f      = (const float*)d_in[11];
    const float* bh_f      = (const float*)d_in[12];
    const float* Wi_b      = (const float*)d_in[13];
    const float* Wh_b      = (const float*)d_in[14];
    const float* bi_b      = (const float*)d_in[15];
    const float* bh_b      = (const float*)d_in[16];

    float* out = (float*)d_out;
    float* emb_out = out + OUT3_O;

    cudaFuncSetAttribute(k_recur, cudaFuncAttributeMaxDynamicSharedMemorySize, SMEM_RECUR);

    k_sniff<<<1, 256>>>((const unsigned int*)act_mask);
    k_init<<<2048, 256>>>(out);
    k_embed<<<(BB * TT * 64 + 255) / 256, 256>>>(act_mask, act_ids, obs_ids,
                                                 act_emb, obs_emb, emb_out);
    k_res<<<(BB * TT) / 64, 256>>>(res_feats, W_res, b_res, act_mask, emb_out);
    {
        dim3 g(G4 / 128, (BB * TT) / 128, 2);
        k_xw<<<g, 256>>>(emb_out, Wi_f, bi_f, bh_f, Wi_b, bi_b, bh_b, lengths);
    }
    k_recur<<<128, 256, SMEM_RECUR>>>(Wh_f, Wh_b, lengths, out);
}